// round 15
// baseline (speedup 1.0000x reference)
#include <cuda_runtime.h>
#include <cuda_bf16.h>
#include <cstdint>

#define NUM_S 1024
#define EPS_F 1e-6f
#define SCALE_F   4096.0f            // 2^12 fixed-point for err2
#define INV_SCALE (1.0f/4096.0f)
#define CNT_ONE   (1u << 25)         // count lives in bits [25:32)
#define SSE_MASK  ((1u << 25) - 1)   // sse fixed-point in bits [0:25)

#define TILE_V   512                 // vec4 groups per tile (2048 elements)
#define TILE_B   (TILE_V * 16)       // 8192 bytes per array per tile
#define STAGE_B  (3 * TILE_B)        // 24576 bytes per stage
// dynamic smem layout: [hist 4096][stage0 24576][stage1 24576]
#define OFF_HIST 0
#define OFF_STG(s)  (4096 + (s) * STAGE_B)
#define SMEM_BYTES  (4096 + 2 * STAGE_B)   // 53248

// Global scratch (allocation-free rule: __device__ globals).
__device__ float        g_sse[NUM_S];
__device__ float        g_cnt[NUM_S];
__device__ unsigned int g_arrive;

__device__ __forceinline__ unsigned int pack_e(float d) {
    return CNT_ONE | (unsigned int)(fmaf(d, d, 0.0f) * SCALE_F + 0.5f);
}

__device__ __forceinline__ uint32_t smem_u32(const void* p) {
    return (uint32_t)__cvta_generic_to_shared(p);
}

__device__ __forceinline__ void bulk_g2s(uint32_t dst, const void* src,
                                         int bytes, uint32_t bar) {
    asm volatile(
        "cp.async.bulk.shared::cta.global.mbarrier::complete_tx::bytes "
        "[%0], [%1], %2, [%3];"
        :: "r"(dst), "l"(src), "r"(bytes), "r"(bar) : "memory");
}

__device__ __forceinline__ void mbar_init(uint32_t bar, unsigned cnt) {
    asm volatile("mbarrier.init.shared.b64 [%0], %1;" :: "r"(bar), "r"(cnt) : "memory");
}
__device__ __forceinline__ void mbar_expect_tx(uint32_t bar, unsigned bytes) {
    asm volatile("mbarrier.arrive.expect_tx.shared.b64 _, [%0], %1;"
                 :: "r"(bar), "r"(bytes) : "memory");
}
__device__ __forceinline__ void mbar_wait_parity(uint32_t bar, unsigned phase) {
    asm volatile(
        "{\n\t"
        ".reg .pred P;\n\t"
        "WAIT_%=:\n\t"
        "mbarrier.try_wait.parity.acquire.cta.shared::cta.b64 P, [%0], %1, 0x989680;\n\t"
        "@P bra.uni DONE_%=;\n\t"
        "bra.uni WAIT_%=;\n\t"
        "DONE_%=:\n\t"
        "}"
        :: "r"(bar), "r"(phase) : "memory");
}

__global__ __launch_bounds__(256, 4)
void nse_fused_kernel(const float4* __restrict__ yp,
                      const float4* __restrict__ yt,
                      const int4*  __restrict__ st,
                      int nvec, int per_block,
                      const float* __restrict__ yp_s,
                      const float* __restrict__ yt_s,
                      const int*   __restrict__ st_s,
                      int rem_start, int n_total,
                      const float* __restrict__ station_std,
                      float* __restrict__ out)
{
    extern __shared__ char smem[];
    unsigned int* hist = (unsigned int*)(smem + OFF_HIST);
    __shared__ unsigned long long mbar_store[2];
    __shared__ float red_s[8];
    __shared__ float red_c[8];
    __shared__ int   s_is_last;

    const int tid = threadIdx.x;
    const uint32_t bar0 = smem_u32(&mbar_store[0]);
    const uint32_t bar1 = smem_u32(&mbar_store[1]);
    const uint32_t smem_base = smem_u32(smem);

    #pragma unroll
    for (int i = tid; i < NUM_S; i += 256) hist[i] = 0u;
    if (tid == 0) { mbar_init(bar0, 1); mbar_init(bar1, 1); }
    __syncthreads();

    // ---- contiguous slab for this block ----
    const int v_begin = blockIdx.x * per_block;
    const int v_end   = min(v_begin + per_block, nvec);
    const int ntiles  = (v_end > v_begin) ? (v_end - v_begin + TILE_V - 1) / TILE_V : 0;

    // ---- producer helper (thread 0): issue 3 bulk copies for tile t into stage s
    auto issue = [&](int t, int s) {
        const int v0    = v_begin + t * TILE_V;
        const int cnt   = min(TILE_V, v_end - v0);
        const int bytes = cnt * 16;
        const uint32_t bar = (s == 0) ? bar0 : bar1;
        const uint32_t dst = smem_base + OFF_STG(s);
        mbar_expect_tx(bar, 3u * (unsigned)bytes);
        bulk_g2s(dst,              yp + v0, bytes, bar);
        bulk_g2s(dst + TILE_B,     yt + v0, bytes, bar);
        bulk_g2s(dst + 2 * TILE_B, st + v0, bytes, bar);
    };

    if (tid == 0) {
        if (ntiles > 0) issue(0, 0);
        if (ntiles > 1) issue(1, 1);
    }

    for (int t = 0; t < ntiles; ++t) {
        const int s = t & 1;
        mbar_wait_parity((s == 0) ? bar0 : bar1, (unsigned)((t >> 1) & 1));

        const int v0  = v_begin + t * TILE_V;
        const int cnt = min(TILE_V, v_end - v0);
        const float4* sp = (const float4*)(smem + OFF_STG(s));
        const float4* stt = (const float4*)(smem + OFF_STG(s) + TILE_B);
        const int4*   ssi = (const int4*)  (smem + OFF_STG(s) + 2 * TILE_B);

        for (int v = tid; v < cnt; v += 256) {
            float4 p = sp[v];
            float4 q = stt[v];
            int4   si = ssi[v];
            atomicAdd(&hist[si.x], pack_e(p.x - q.x));
            atomicAdd(&hist[si.y], pack_e(p.y - q.y));
            atomicAdd(&hist[si.z], pack_e(p.z - q.z));
            atomicAdd(&hist[si.w], pack_e(p.w - q.w));
        }
        __syncthreads();                   // all reads of stage s done
        if (tid == 0 && t + 2 < ntiles) issue(t + 2, s);
    }

    // ---- scalar tail (N % 4) straight to global accumulators ----
    {
        const int gtid    = blockIdx.x * 256 + tid;
        const int gstride = gridDim.x * 256;
        for (int k = rem_start + gtid; k < n_total; k += gstride) {
            float d = yp_s[k] - yt_s[k];
            atomicAdd(&g_sse[st_s[k]], d * d);
            atomicAdd(&g_cnt[st_s[k]], 1.0f);
        }
    }

    // ---- flush block histogram to global ----
    __syncthreads();
    #pragma unroll
    for (int k = tid; k < NUM_S; k += 256) {
        unsigned int v = hist[k];
        if (v) {
            atomicAdd(&g_cnt[k], (float)(v >> 25));
            atomicAdd(&g_sse[k], (float)(v & SSE_MASK) * INV_SCALE);
        }
    }
    __syncthreads();

    // ---- last-block fused finalize ----
    __threadfence();
    if (tid == 0) {
        unsigned int old = atomicAdd(&g_arrive, 1u);
        s_is_last = (old == gridDim.x - 1u) ? 1 : 0;
    }
    __syncthreads();
    if (!s_is_last) return;

    float per = 0.0f, pres = 0.0f;
    #pragma unroll
    for (int k = tid; k < NUM_S; k += 256) {
        float sse = g_sse[k];
        float cnt = g_cnt[k];
        g_sse[k] = 0.0f;           // self-restore for next replay
        g_cnt[k] = 0.0f;
        float sd = station_std[k] + EPS_F;
        if (cnt > 0.0f) {
            per  += (sse / cnt) / (sd * sd);
            pres += 1.0f;
        }
    }
    #pragma unroll
    for (int o = 16; o > 0; o >>= 1) {
        per  += __shfl_down_sync(0xFFFFFFFFu, per,  o);
        pres += __shfl_down_sync(0xFFFFFFFFu, pres, o);
    }
    if ((tid & 31) == 0) {
        red_s[tid >> 5] = per;
        red_c[tid >> 5] = pres;
    }
    __syncthreads();
    if (tid < 32) {
        per  = (tid < 8) ? red_s[tid] : 0.0f;
        pres = (tid < 8) ? red_c[tid] : 0.0f;
        #pragma unroll
        for (int o = 4; o > 0; o >>= 1) {
            per  += __shfl_down_sync(0xFFFFFFFFu, per,  o);
            pres += __shfl_down_sync(0xFFFFFFFFu, pres, o);
        }
        if (tid == 0) {
            out[0] = per / fmaxf(pres, 1.0f);
            g_arrive = 0u;          // self-restore for next replay
        }
    }
}

extern "C" void kernel_launch(void* const* d_in, const int* in_sizes, int n_in,
                              void* d_out, int out_size)
{
    const float* y_pred      = (const float*)d_in[0];
    const float* y_true      = (const float*)d_in[1];
    const int*   stations    = (const int*)d_in[2];
    const float* station_std = (const float*)d_in[3];
    float* out = (float*)d_out;

    const int n         = in_sizes[0];
    const int nvec      = n / 4;
    const int rem_start = nvec * 4;

    const int block = 256;
    const int grid  = 592;   // 148 SMs x 4 resident blocks -> exactly one wave
    const int per_block = (nvec + grid - 1) / grid;

    static int smem_set = 0;
    if (!smem_set) {
        cudaFuncSetAttribute(nse_fused_kernel,
                             cudaFuncAttributeMaxDynamicSharedMemorySize,
                             SMEM_BYTES);
        smem_set = 1;
    }

    nse_fused_kernel<<<grid, block, SMEM_BYTES>>>(
        (const float4*)y_pred, (const float4*)y_true, (const int4*)stations,
        nvec, per_block, y_pred, y_true, stations, rem_start, n,
        station_std, out);
}